// round 8
// baseline (speedup 1.0000x reference)
#include <cuda_runtime.h>
#include <cuda_fp16.h>
#include <math.h>
#include <stdint.h>

// ============================================================================
// MLA prefill — round 8: fp16 split-precision GEMMs with PRE-SPLIT operands.
// Round 7 (split-in-mainloop) passed at 2784us, rel_err 2.1e-5, tensor=46.6%.
// This round hoists all fp32->fp16(hi,lo) conversion out of the GEMM mainloop:
// every operand lives in global as separate hi/lo __half arrays; producer
// kernels (GEMM epilogues, softmax, transposes) emit halves directly.
// Mainloop = pure LDS.32 + HMMA.16816 (3-pass: hh + hl + lh).
// ============================================================================

#define SB     2
#define SEQL   2048
#define DMODEL 2048
#define CLAT   512
#define NH     16
#define DHD    128
#define HDTOT  2048

// ---------------- scratch ----------------
// weights / inputs (hi/lo halves)
__device__ __half g_xh [(size_t)SB * SEQL * DMODEL],  g_xl [(size_t)SB * SEQL * DMODEL];
__device__ __half g_wdh[(size_t)CLAT * DMODEL],       g_wdl[(size_t)CLAT * DMODEL];
__device__ __half g_wqh[(size_t)HDTOT * DMODEL],      g_wql[(size_t)HDTOT * DMODEL];
__device__ __half g_wuvh[(size_t)HDTOT * CLAT],       g_wuvl[(size_t)HDTOT * CLAT];
__device__ __half g_woh[(size_t)DMODEL * HDTOT],      g_wol[(size_t)DMODEL * HDTOT];
__device__ __half g_wukTh[(size_t)NH * CLAT * DHD],   g_wukTl[(size_t)NH * CLAT * DHD];
// intermediates
__device__ float  g_lat  [(size_t)SB * SEQL * CLAT];
__device__ __half g_lath [(size_t)SB * SEQL * CLAT],  g_latl [(size_t)SB * SEQL * CLAT];
__device__ __half g_latTh[(size_t)SB * CLAT * SEQL],  g_latTl[(size_t)SB * CLAT * SEQL];
__device__ __half g_qh   [(size_t)SB * SEQL * HDTOT], g_ql   [(size_t)SB * SEQL * HDTOT];
__device__ __half g_qlath[(size_t)SB * NH * SEQL * CLAT], g_qlatl[(size_t)SB * NH * SEQL * CLAT];
__device__ float  g_scores[(size_t)SB * NH * SEQL * SEQL];                 // 512 MB
__device__ __half g_attnh[(size_t)SB * NH * SEQL * SEQL], g_attnl[(size_t)SB * NH * SEQL * SEQL];
__device__ __half g_ctxh [(size_t)SB * NH * SEQL * CLAT], g_ctxl [(size_t)SB * NH * SEQL * CLAT];
__device__ __half g_vh   [(size_t)SB * SEQL * HDTOT], g_vl   [(size_t)SB * SEQL * HDTOT];

#define BM 128
#define BN 128
#define BK 16
#define ROWH 24      // smem row pitch in halves (16 data + 8 pad): bank-conflict-free

// m16n8k16 fp16 mma, fp32 accumulate.
static __device__ __forceinline__ void mma_16816(float* d, const uint32_t* a,
                                                 const uint32_t* b) {
    asm volatile(
        "mma.sync.aligned.m16n8k16.row.col.f32.f16.f16.f32 "
        "{%0,%1,%2,%3}, {%4,%5,%6,%7}, {%8,%9}, {%0,%1,%2,%3};"
        : "+f"(d[0]), "+f"(d[1]), "+f"(d[2]), "+f"(d[3])
        : "r"(a[0]), "r"(a[1]), "r"(a[2]), "r"(a[3]), "r"(b[0]), "r"(b[1]));
}

static __device__ __forceinline__ void fsplit(float f, __half& h, __half& l) {
    h = __float2half_rn(f);
    l = __float2half_rn(f - __half2float(h));
}

// cp.async one 16B chunk per thread into a 128x16-half tile (pitch ROWH).
static __device__ __forceinline__ void pf_tile(__half* s, const __half* g, int ld, int tid) {
    const int r = tid >> 1;
    const int c = (tid & 1) << 3;       // 0 or 8 halves
    unsigned dst = (unsigned)__cvta_generic_to_shared(s + r * ROWH + c);
    asm volatile("cp.async.cg.shared.global [%0], [%1], 16;"
                 :: "r"(dst), "l"(g + (long long)r * ld + c));
}

// ---------------------------------------------------------------------------
// GEMM: C[128m,128n] = alpha * A @ B^T, A[M,K] hi/lo halves, B[N,K] hi/lo.
// MODE 0: plain. 1: G3. 2: G4 (causal skip). 3: G6 (K_eff). 4: G7.
// OUTK 0: fp32 C. 1: hi/lo half C. 2: both (fp32 + halves).
// 256 threads = 8 warps (2m x 4n); warp tile 64x32 = 4x4 m16n8k16 atoms.
// ---------------------------------------------------------------------------
template<int MODE, int OUTK>
__global__ void __launch_bounds__(256)
mma_gemm(const __half* __restrict__ Ah, const __half* __restrict__ Al,
         const __half* __restrict__ Bh, const __half* __restrict__ Bl,
         float* __restrict__ C, __half* __restrict__ Ch, __half* __restrict__ Cl,
         int K, int lda, int ldb, int ldc, float alpha)
{
    const int bn = blockIdx.x;
    const int bm = blockIdx.y;
    const int z  = blockIdx.z;

    if (MODE == 2 && bn > bm) return;      // causal: whole block above diagonal

    long long aoff = 0, boff = 0, coff = 0;
    if (MODE == 1) {
        int b = z >> 4, h = z & 15;
        aoff = (long long)b * SEQL * HDTOT + (long long)h * DHD;
        boff = (long long)h * CLAT * DHD;
        coff = (long long)z * SEQL * CLAT;
    } else if (MODE == 2) {
        aoff = (long long)z * SEQL * CLAT;
        boff = (long long)(z >> 4) * SEQL * CLAT;
        coff = (long long)z * SEQL * SEQL;
    } else if (MODE == 3) {
        aoff = (long long)z * SEQL * SEQL;
        boff = (long long)(z >> 4) * CLAT * SEQL;
        coff = (long long)z * SEQL * CLAT;
    } else if (MODE == 4) {
        int b = z >> 4, h = z & 15;
        aoff = (long long)z * SEQL * CLAT;
        boff = (long long)h * DHD * CLAT;
        coff = (long long)b * SEQL * HDTOT + (long long)h * DHD;
    }

    const int Keff = (MODE == 3) ? min(K, (bm + 1) * BM) : K;
    const int nkt = Keff / BK;

    const __half* Abh = Ah + aoff + (long long)bm * BM * lda;
    const __half* Abl = Al + aoff + (long long)bm * BM * lda;
    const __half* Bbh = Bh + boff + (long long)bn * BN * ldb;
    const __half* Bbl = Bl + boff + (long long)bn * BN * ldb;
    const long long cbase = coff + (long long)bm * BM * ldc + (long long)bn * BN;

    // [buf][0=Ahi 1=Alo 2=Bhi 3=Blo][BM*ROWH]
    __shared__ __half sm[2][4][BM * ROWH];

    const int tid  = threadIdx.x;
    const int lane = tid & 31;
    const int w    = tid >> 5;
    const int mo = (w >> 2) * 64;          // warp m offset (0/64)
    const int no = (w & 3) * 32;           // warp n offset (0/32/64/96)
    const int g  = lane >> 2;              // group 0..7
    const int t  = lane & 3;               // thread-in-group 0..3

    float acc[4][4][4];
#pragma unroll
    for (int mt = 0; mt < 4; mt++)
#pragma unroll
        for (int nt = 0; nt < 4; nt++)
#pragma unroll
            for (int e = 0; e < 4; e++) acc[mt][nt][e] = 0.f;

    // prologue
    pf_tile(sm[0][0], Abh, lda, tid);
    pf_tile(sm[0][1], Abl, lda, tid);
    pf_tile(sm[0][2], Bbh, ldb, tid);
    pf_tile(sm[0][3], Bbl, ldb, tid);
    asm volatile("cp.async.commit_group;");

    for (int kt = 0; kt < nkt; ++kt) {
        const int buf = kt & 1;
        if (kt + 1 < nkt) {
            const long long ko = (long long)(kt + 1) * BK;
            pf_tile(sm[buf ^ 1][0], Abh + ko, lda, tid);
            pf_tile(sm[buf ^ 1][1], Abl + ko, lda, tid);
            pf_tile(sm[buf ^ 1][2], Bbh + ko, ldb, tid);
            pf_tile(sm[buf ^ 1][3], Bbl + ko, ldb, tid);
            asm volatile("cp.async.commit_group;");
            asm volatile("cp.async.wait_group 1;");
        } else {
            asm volatile("cp.async.wait_group 0;");
        }
        __syncthreads();

        const __half* Ahb = sm[buf][0];
        const __half* Alb = sm[buf][1];
        const __half* Bhb = sm[buf][2];
        const __half* Blb = sm[buf][3];

        uint32_t ah[4][4], al[4][4], bh[4][2], bl[4][2];
#pragma unroll
        for (int mt = 0; mt < 4; mt++) {
            const int base = (mo + mt * 16 + g) * ROWH + 2 * t;
            ah[mt][0] = *reinterpret_cast<const uint32_t*>(Ahb + base);
            ah[mt][1] = *reinterpret_cast<const uint32_t*>(Ahb + base + 8 * ROWH);
            ah[mt][2] = *reinterpret_cast<const uint32_t*>(Ahb + base + 8);
            ah[mt][3] = *reinterpret_cast<const uint32_t*>(Ahb + base + 8 * ROWH + 8);
            al[mt][0] = *reinterpret_cast<const uint32_t*>(Alb + base);
            al[mt][1] = *reinterpret_cast<const uint32_t*>(Alb + base + 8 * ROWH);
            al[mt][2] = *reinterpret_cast<const uint32_t*>(Alb + base + 8);
            al[mt][3] = *reinterpret_cast<const uint32_t*>(Alb + base + 8 * ROWH + 8);
        }
#pragma unroll
        for (int nt = 0; nt < 4; nt++) {
            const int base = (no + nt * 8 + g) * ROWH + 2 * t;
            bh[nt][0] = *reinterpret_cast<const uint32_t*>(Bhb + base);
            bh[nt][1] = *reinterpret_cast<const uint32_t*>(Bhb + base + 8);
            bl[nt][0] = *reinterpret_cast<const uint32_t*>(Blb + base);
            bl[nt][1] = *reinterpret_cast<const uint32_t*>(Blb + base + 8);
        }

        // 3-pass split-precision mma: hi*hi + hi*lo + lo*hi
#pragma unroll
        for (int mt = 0; mt < 4; mt++)
#pragma unroll
            for (int nt = 0; nt < 4; nt++) {
                mma_16816(acc[mt][nt], ah[mt], bh[nt]);
                mma_16816(acc[mt][nt], ah[mt], bl[nt]);
                mma_16816(acc[mt][nt], al[mt], bh[nt]);
            }
        __syncthreads();
    }

    // epilogue: c0/c1 at (g, 2t..2t+1), c2/c3 at (g+8, 2t..2t+1)
#pragma unroll
    for (int mt = 0; mt < 4; mt++) {
        const int r0 = mo + mt * 16 + g;
#pragma unroll
        for (int nt = 0; nt < 4; nt++) {
            const int ccol = no + nt * 8 + 2 * t;
            const long long i0 = cbase + (long long)r0 * ldc + ccol;
            const long long i1 = cbase + (long long)(r0 + 8) * ldc + ccol;
            float f0 = acc[mt][nt][0] * alpha, f1 = acc[mt][nt][1] * alpha;
            float f2 = acc[mt][nt][2] * alpha, f3 = acc[mt][nt][3] * alpha;
            if (OUTK == 0 || OUTK == 2) {
                *reinterpret_cast<float2*>(C + i0) = make_float2(f0, f1);
                *reinterpret_cast<float2*>(C + i1) = make_float2(f2, f3);
            }
            if (OUTK == 1 || OUTK == 2) {
                __half h0, l0, h1, l1, h2, l2, h3, l3;
                fsplit(f0, h0, l0); fsplit(f1, h1, l1);
                fsplit(f2, h2, l2); fsplit(f3, h3, l3);
                *reinterpret_cast<__half2*>(Ch + i0) = __halves2half2(h0, h1);
                *reinterpret_cast<__half2*>(Cl + i0) = __halves2half2(l0, l1);
                *reinterpret_cast<__half2*>(Ch + i1) = __halves2half2(h2, h3);
                *reinterpret_cast<__half2*>(Cl + i1) = __halves2half2(l2, l3);
            }
        }
    }
}

// ---------------------------------------------------------------------------
// Elementwise fp32 -> (hi, lo) halves.
// ---------------------------------------------------------------------------
__global__ void cvt_kernel(const float* __restrict__ in, __half* __restrict__ oh,
                           __half* __restrict__ ol, long long n)
{
    long long i = (long long)blockIdx.x * blockDim.x + threadIdx.x;
    if (i < n) {
        __half h, l;
        fsplit(in[i], h, l);
        oh[i] = h; ol[i] = l;
    }
}

// ---------------------------------------------------------------------------
// 32x32 transpose + split:  fp32 in [z][R][C] -> hi/lo halves [z][C][R]
// ---------------------------------------------------------------------------
__global__ void transpose_cvt_kernel(const float* __restrict__ in,
                                     __half* __restrict__ oh, __half* __restrict__ ol,
                                     int R, int Cc)
{
    __shared__ float tsm[32][33];
    const int z = blockIdx.z;
    const int r0 = blockIdx.y * 32, c0 = blockIdx.x * 32;
    const float* I = in + (long long)z * R * Cc;
    const long long obase = (long long)z * R * Cc;
    const int tx = threadIdx.x, ty = threadIdx.y;
#pragma unroll
    for (int i = 0; i < 32; i += 8)
        tsm[ty + i][tx] = I[(long long)(r0 + ty + i) * Cc + c0 + tx];
    __syncthreads();
#pragma unroll
    for (int i = 0; i < 32; i += 8) {
        __half h, l;
        fsplit(tsm[tx][ty + i], h, l);
        long long o = obase + (long long)(c0 + ty + i) * R + r0 + tx;
        oh[o] = h; ol[o] = l;
    }
}

// ---------------------------------------------------------------------------
// Causal row softmax: fp32 scores -> hi/lo half probs, zeros to 128 boundary.
// ---------------------------------------------------------------------------
__global__ void softmax_kernel(const float* __restrict__ scores,
                               __half* __restrict__ ph, __half* __restrict__ pl)
{
    const int warp = threadIdx.x >> 5;
    const int lane = threadIdx.x & 31;
    const long long r = (long long)blockIdx.x * (blockDim.x >> 5) + warp;
    const int s = (int)(r & (SEQL - 1));
    const int len = s + 1;
    const float* row = scores + r * SEQL;
    __half* rh = ph + r * SEQL;
    __half* rl = pl + r * SEQL;

    float mx = -INFINITY;
    for (int j = lane; j < len; j += 32) mx = fmaxf(mx, row[j]);
#pragma unroll
    for (int o = 16; o > 0; o >>= 1) mx = fmaxf(mx, __shfl_xor_sync(0xffffffffu, mx, o));

    float sum = 0.f;
    for (int j = lane; j < len; j += 32) sum += __expf(row[j] - mx);
#pragma unroll
    for (int o = 16; o > 0; o >>= 1) sum += __shfl_xor_sync(0xffffffffu, sum, o);

    const float inv = 1.0f / sum;
    for (int j = lane; j < len; j += 32) {
        float p = __expf(row[j] - mx) * inv;
        __half h, l;
        fsplit(p, h, l);
        rh[j] = h; rl[j] = l;
    }
    const int zend = ((s >> 7) + 1) << 7;
    for (int j = len + lane; j < zend; j += 32) {
        rh[j] = __float2half_rn(0.f); rl[j] = __float2half_rn(0.f);
    }
}

// ---------------------------------------------------------------------------
extern "C" void kernel_launch(void* const* d_in, const int* in_sizes, int n_in,
                              void* d_out, int out_size)
{
    const float* x   = (const float*)d_in[0];
    const float* Wd  = (const float*)d_in[1];
    const float* Wuk = (const float*)d_in[2];
    const float* Wuv = (const float*)d_in[3];
    const float* Wq  = (const float*)d_in[4];
    const float* Wo  = (const float*)d_in[5];
    float* out = (float*)d_out;

#define SYM(p, s) cudaGetSymbolAddress((void**)&p, s)
    __half *xh, *xl, *wdh, *wdl, *wqh, *wql, *wuvh, *wuvl, *woh, *wol, *wukTh, *wukTl;
    __half *lath, *latl, *latTh, *latTl, *qh, *ql, *qlath, *qlatl;
    __half *attnh, *attnl, *ctxh, *ctxl, *vh, *vl;
    float *lat, *sc;
    SYM(xh, g_xh); SYM(xl, g_xl); SYM(wdh, g_wdh); SYM(wdl, g_wdl);
    SYM(wqh, g_wqh); SYM(wql, g_wql); SYM(wuvh, g_wuvh); SYM(wuvl, g_wuvl);
    SYM(woh, g_woh); SYM(wol, g_wol); SYM(wukTh, g_wukTh); SYM(wukTl, g_wukTl);
    SYM(lat, g_lat); SYM(lath, g_lath); SYM(latl, g_latl);
    SYM(latTh, g_latTh); SYM(latTl, g_latTl);
    SYM(qh, g_qh); SYM(ql, g_ql); SYM(qlath, g_qlath); SYM(qlatl, g_qlatl);
    SYM(sc, g_scores); SYM(attnh, g_attnh); SYM(attnl, g_attnl);
    SYM(ctxh, g_ctxh); SYM(ctxl, g_ctxl); SYM(vh, g_vh); SYM(vl, g_vl);
#undef SYM

    const int MROWS = SB * SEQL;  // 4096
    const dim3 blk(256);
    const float inv_sqrt_dh = 0.08838834764831845f;

    // C0: split inputs/weights
    {
        long long n;
        n = (long long)SB * SEQL * DMODEL;
        cvt_kernel<<<(unsigned)((n + 255) / 256), 256>>>(x, xh, xl, n);
        n = (long long)CLAT * DMODEL;
        cvt_kernel<<<(unsigned)((n + 255) / 256), 256>>>(Wd, wdh, wdl, n);
        n = (long long)HDTOT * DMODEL;
        cvt_kernel<<<(unsigned)((n + 255) / 256), 256>>>(Wq, wqh, wql, n);
        n = (long long)HDTOT * CLAT;
        cvt_kernel<<<(unsigned)((n + 255) / 256), 256>>>(Wuv, wuvh, wuvl, n);
        n = (long long)DMODEL * HDTOT;
        cvt_kernel<<<(unsigned)((n + 255) / 256), 256>>>(Wo, woh, wol, n);
    }
    // T2: wukT halves  (Wuk [h][DHD][CLAT] -> [h][CLAT][DHD])
    transpose_cvt_kernel<<<dim3(CLAT / 32, DHD / 32, NH), dim3(32, 8)>>>(
        Wuk, wukTh, wukTl, DHD, CLAT);

    // G1: latents = x @ Wd^T   (fp32 + halves)
    mma_gemm<0, 2><<<dim3(CLAT / BN, MROWS / BM, 1), blk>>>(
        xh, xl, wdh, wdl, lat, lath, latl, DMODEL, DMODEL, DMODEL, CLAT, 1.f);

    // T1: latT halves
    transpose_cvt_kernel<<<dim3(CLAT / 32, SEQL / 32, SB), dim3(32, 8)>>>(
        lat, latTh, latTl, SEQL, CLAT);

    // G2: q = x @ Wq^T  (halves out)
    mma_gemm<0, 1><<<dim3(HDTOT / BN, MROWS / BM, 1), blk>>>(
        xh, xl, wqh, wql, nullptr, qh, ql, DMODEL, DMODEL, DMODEL, HDTOT, 1.f);

    // G3: q_lat[z] = q_h @ wukT[h]^T   (K=128, halves out)
    mma_gemm<1, 1><<<dim3(CLAT / BN, SEQL / BM, SB * NH), blk>>>(
        qh, ql, wukTh, wukTl, nullptr, qlath, qlatl, DHD, HDTOT, DHD, CLAT, 1.f);

    // G4: scores = q_lat @ latents^T / sqrt(dh)  (causal, fp32 out)
    mma_gemm<2, 0><<<dim3(SEQL / BN, SEQL / BM, SB * NH), blk>>>(
        qlath, qlatl, lath, latl, sc, nullptr, nullptr, CLAT, CLAT, CLAT, SEQL, inv_sqrt_dh);

    // G5: softmax -> attn halves
    softmax_kernel<<<(unsigned)((long long)SB * NH * SEQL / 8), 256>>>(sc, attnh, attnl);

    // G6: ctx = attn @ latT^T  (K_eff per row tile, halves out)
    mma_gemm<3, 1><<<dim3(CLAT / BN, SEQL / BM, SB * NH), blk>>>(
        attnh, attnl, latTh, latTl, nullptr, ctxh, ctxl, SEQL, SEQL, SEQL, CLAT, 1.f);

    // G7: v_h = ctx @ Wuv_h^T  (halves out)
    mma_gemm<4, 1><<<dim3(DHD / BN, SEQL / BM, SB * NH), blk>>>(
        ctxh, ctxl, wuvh, wuvl, nullptr, vh, vl, CLAT, CLAT, CLAT, HDTOT, 1.f);

    // G8: out = v @ Wo^T  (fp32 out)
    mma_gemm<0, 0><<<dim3(DMODEL / BN, MROWS / BM, 1), blk>>>(
        vh, vl, woh, wol, out, nullptr, nullptr, HDTOT, HDTOT, HDTOT, DMODEL, 1.f);
}

// round 10
// speedup vs baseline: 1.1601x; 1.1601x over previous
#include <cuda_runtime.h>
#include <cuda_fp16.h>
#include <math.h>
#include <stdint.h>

// ============================================================================
// MLA prefill — round 10: R9 fixed (dynamic smem for the 80KB BK=32 tiles).
//   (1) single-exp two-pass softmax (undo R8's doubled MUFU work)
//   (2) BK=32 (half the syncs, 64B-coalesced cp.async)
// Pre-split fp16 hi/lo operands; 3-pass split mma (hh+hl+lh), fp32 accumulate.
// ============================================================================

#define SB     2
#define SEQL   2048
#define DMODEL 2048
#define CLAT   512
#define NH     16
#define DHD    128
#define HDTOT  2048

// ---------------- scratch ----------------
__device__ __half g_xh [(size_t)SB * SEQL * DMODEL],  g_xl [(size_t)SB * SEQL * DMODEL];
__device__ __half g_wdh[(size_t)CLAT * DMODEL],       g_wdl[(size_t)CLAT * DMODEL];
__device__ __half g_wqh[(size_t)HDTOT * DMODEL],      g_wql[(size_t)HDTOT * DMODEL];
__device__ __half g_wuvh[(size_t)HDTOT * CLAT],       g_wuvl[(size_t)HDTOT * CLAT];
__device__ __half g_woh[(size_t)DMODEL * HDTOT],      g_wol[(size_t)DMODEL * HDTOT];
__device__ __half g_wukTh[(size_t)NH * CLAT * DHD],   g_wukTl[(size_t)NH * CLAT * DHD];
__device__ float  g_lat  [(size_t)SB * SEQL * CLAT];
__device__ __half g_lath [(size_t)SB * SEQL * CLAT],  g_latl [(size_t)SB * SEQL * CLAT];
__device__ __half g_latTh[(size_t)SB * CLAT * SEQL],  g_latTl[(size_t)SB * CLAT * SEQL];
__device__ __half g_qh   [(size_t)SB * SEQL * HDTOT], g_ql   [(size_t)SB * SEQL * HDTOT];
__device__ __half g_qlath[(size_t)SB * NH * SEQL * CLAT], g_qlatl[(size_t)SB * NH * SEQL * CLAT];
__device__ float  g_scores[(size_t)SB * NH * SEQL * SEQL];
__device__ __half g_attnh[(size_t)SB * NH * SEQL * SEQL], g_attnl[(size_t)SB * NH * SEQL * SEQL];
__device__ __half g_ctxh [(size_t)SB * NH * SEQL * CLAT], g_ctxl [(size_t)SB * NH * SEQL * CLAT];
__device__ __half g_vh   [(size_t)SB * SEQL * HDTOT], g_vl   [(size_t)SB * SEQL * HDTOT];

#define BM 128
#define BN 128
#define BK 32
#define ROWH 40      // smem row pitch in halves (32 data + 8 pad): conflict-free
#define TILEH (BM * ROWH)                       // halves per operand tile
#define SMEM_BYTES (2 * 4 * TILEH * 2)          // 81920 B

// m16n8k16 fp16 mma, fp32 accumulate.
static __device__ __forceinline__ void mma_16816(float* d, const uint32_t* a,
                                                 const uint32_t* b) {
    asm volatile(
        "mma.sync.aligned.m16n8k16.row.col.f32.f16.f16.f32 "
        "{%0,%1,%2,%3}, {%4,%5,%6,%7}, {%8,%9}, {%0,%1,%2,%3};"
        : "+f"(d[0]), "+f"(d[1]), "+f"(d[2]), "+f"(d[3])
        : "r"(a[0]), "r"(a[1]), "r"(a[2]), "r"(a[3]), "r"(b[0]), "r"(b[1]));
}

static __device__ __forceinline__ void fsplit(float f, __half& h, __half& l) {
    h = __float2half_rn(f);
    l = __float2half_rn(f - __half2float(h));
}

// cp.async one 128x32-half tile (8KB): 512 16B chunks, 2 per thread.
static __device__ __forceinline__ void pf_tile(__half* s, const __half* g, int ld, int tid) {
#pragma unroll
    for (int i = 0; i < 2; i++) {
        const int idx = tid + i * 256;      // 0..511
        const int r = idx >> 2;             // 0..127
        const int c = (idx & 3) << 3;       // 0,8,16,24 halves
        unsigned dst = (unsigned)__cvta_generic_to_shared(s + r * ROWH + c);
        asm volatile("cp.async.cg.shared.global [%0], [%1], 16;"
                     :: "r"(dst), "l"(g + (long long)r * ld + c));
    }
}

// ---------------------------------------------------------------------------
// GEMM: C[128m,128n] = alpha * A @ B^T, A[M,K] hi/lo halves, B[N,K] hi/lo.
// MODE 0: plain. 1: G3. 2: G4 (causal skip). 3: G6 (K_eff). 4: G7.
// OUTK 0: fp32 C. 1: hi/lo half C. 2: both.
// 256 threads = 8 warps (2m x 4n); warp tile 64x32 = 4x4 m16n8k16 atoms.
// ---------------------------------------------------------------------------
template<int MODE, int OUTK>
__global__ void __launch_bounds__(256)
mma_gemm(const __half* __restrict__ Ah, const __half* __restrict__ Al,
         const __half* __restrict__ Bh, const __half* __restrict__ Bl,
         float* __restrict__ C, __half* __restrict__ Ch, __half* __restrict__ Cl,
         int K, int lda, int ldb, int ldc, float alpha)
{
    const int bn = blockIdx.x;
    const int bm = blockIdx.y;
    const int z  = blockIdx.z;

    if (MODE == 2 && bn > bm) return;

    long long aoff = 0, boff = 0, coff = 0;
    if (MODE == 1) {
        int b = z >> 4, h = z & 15;
        aoff = (long long)b * SEQL * HDTOT + (long long)h * DHD;
        boff = (long long)h * CLAT * DHD;
        coff = (long long)z * SEQL * CLAT;
    } else if (MODE == 2) {
        aoff = (long long)z * SEQL * CLAT;
        boff = (long long)(z >> 4) * SEQL * CLAT;
        coff = (long long)z * SEQL * SEQL;
    } else if (MODE == 3) {
        aoff = (long long)z * SEQL * SEQL;
        boff = (long long)(z >> 4) * CLAT * SEQL;
        coff = (long long)z * SEQL * CLAT;
    } else if (MODE == 4) {
        int b = z >> 4, h = z & 15;
        aoff = (long long)z * SEQL * CLAT;
        boff = (long long)h * DHD * CLAT;
        coff = (long long)b * SEQL * HDTOT + (long long)h * DHD;
    }

    const int Keff = (MODE == 3) ? min(K, (bm + 1) * BM) : K;
    const int nkt = Keff / BK;

    const __half* Abh = Ah + aoff + (long long)bm * BM * lda;
    const __half* Abl = Al + aoff + (long long)bm * BM * lda;
    const __half* Bbh = Bh + boff + (long long)bn * BN * ldb;
    const __half* Bbl = Bl + boff + (long long)bn * BN * ldb;
    const long long cbase = coff + (long long)bm * BM * ldc + (long long)bn * BN;

    // dynamic smem: [buf][0=Ahi 1=Alo 2=Bhi 3=Blo][TILEH]
    extern __shared__ __half dynsm[];
#define SMT(buf, op) (dynsm + ((buf) * 4 + (op)) * TILEH)

    const int tid  = threadIdx.x;
    const int lane = tid & 31;
    const int w    = tid >> 5;
    const int mo = (w >> 2) * 64;
    const int no = (w & 3) * 32;
    const int g  = lane >> 2;
    const int t  = lane & 3;

    float acc[4][4][4];
#pragma unroll
    for (int mt = 0; mt < 4; mt++)
#pragma unroll
        for (int nt = 0; nt < 4; nt++)
#pragma unroll
            for (int e = 0; e < 4; e++) acc[mt][nt][e] = 0.f;

    pf_tile(SMT(0, 0), Abh, lda, tid);
    pf_tile(SMT(0, 1), Abl, lda, tid);
    pf_tile(SMT(0, 2), Bbh, ldb, tid);
    pf_tile(SMT(0, 3), Bbl, ldb, tid);
    asm volatile("cp.async.commit_group;");

    for (int kt = 0; kt < nkt; ++kt) {
        const int buf = kt & 1;
        if (kt + 1 < nkt) {
            const long long ko = (long long)(kt + 1) * BK;
            pf_tile(SMT(buf ^ 1, 0), Abh + ko, lda, tid);
            pf_tile(SMT(buf ^ 1, 1), Abl + ko, lda, tid);
            pf_tile(SMT(buf ^ 1, 2), Bbh + ko, ldb, tid);
            pf_tile(SMT(buf ^ 1, 3), Bbl + ko, ldb, tid);
            asm volatile("cp.async.commit_group;");
            asm volatile("cp.async.wait_group 1;");
        } else {
            asm volatile("cp.async.wait_group 0;");
        }
        __syncthreads();

        const __half* Ahb = SMT(buf, 0);
        const __half* Alb = SMT(buf, 1);
        const __half* Bhb = SMT(buf, 2);
        const __half* Blb = SMT(buf, 3);

#pragma unroll
        for (int ks = 0; ks < 2; ks++) {        // two k16 steps per BK=32 tile
            const int kk = ks * 16;
            uint32_t ah[4][4], al[4][4], bh[4][2], bl[4][2];
#pragma unroll
            for (int mt = 0; mt < 4; mt++) {
                const int base = (mo + mt * 16 + g) * ROWH + kk + 2 * t;
                ah[mt][0] = *reinterpret_cast<const uint32_t*>(Ahb + base);
                ah[mt][1] = *reinterpret_cast<const uint32_t*>(Ahb + base + 8 * ROWH);
                ah[mt][2] = *reinterpret_cast<const uint32_t*>(Ahb + base + 8);
                ah[mt][3] = *reinterpret_cast<const uint32_t*>(Ahb + base + 8 * ROWH + 8);
                al[mt][0] = *reinterpret_cast<const uint32_t*>(Alb + base);
                al[mt][1] = *reinterpret_cast<const uint32_t*>(Alb + base + 8 * ROWH);
                al[mt][2] = *reinterpret_cast<const uint32_t*>(Alb + base + 8);
                al[mt][3] = *reinterpret_cast<const uint32_t*>(Alb + base + 8 * ROWH + 8);
            }
#pragma unroll
            for (int nt = 0; nt < 4; nt++) {
                const int base = (no + nt * 8 + g) * ROWH + kk + 2 * t;
                bh[nt][0] = *reinterpret_cast<const uint32_t*>(Bhb + base);
                bh[nt][1] = *reinterpret_cast<const uint32_t*>(Bhb + base + 8);
                bl[nt][0] = *reinterpret_cast<const uint32_t*>(Blb + base);
                bl[nt][1] = *reinterpret_cast<const uint32_t*>(Blb + base + 8);
            }
#pragma unroll
            for (int mt = 0; mt < 4; mt++)
#pragma unroll
                for (int nt = 0; nt < 4; nt++) {
                    mma_16816(acc[mt][nt], ah[mt], bh[nt]);
                    mma_16816(acc[mt][nt], ah[mt], bl[nt]);
                    mma_16816(acc[mt][nt], al[mt], bh[nt]);
                }
        }
        __syncthreads();
    }
#undef SMT

#pragma unroll
    for (int mt = 0; mt < 4; mt++) {
        const int r0 = mo + mt * 16 + g;
#pragma unroll
        for (int nt = 0; nt < 4; nt++) {
            const int ccol = no + nt * 8 + 2 * t;
            const long long i0 = cbase + (long long)r0 * ldc + ccol;
            const long long i1 = cbase + (long long)(r0 + 8) * ldc + ccol;
            float f0 = acc[mt][nt][0] * alpha, f1 = acc[mt][nt][1] * alpha;
            float f2 = acc[mt][nt][2] * alpha, f3 = acc[mt][nt][3] * alpha;
            if (OUTK == 0 || OUTK == 2) {
                *reinterpret_cast<float2*>(C + i0) = make_float2(f0, f1);
                *reinterpret_cast<float2*>(C + i1) = make_float2(f2, f3);
            }
            if (OUTK == 1 || OUTK == 2) {
                __half h0, l0, h1, l1, h2, l2, h3, l3;
                fsplit(f0, h0, l0); fsplit(f1, h1, l1);
                fsplit(f2, h2, l2); fsplit(f3, h3, l3);
                *reinterpret_cast<__half2*>(Ch + i0) = __halves2half2(h0, h1);
                *reinterpret_cast<__half2*>(Cl + i0) = __halves2half2(l0, l1);
                *reinterpret_cast<__half2*>(Ch + i1) = __halves2half2(h2, h3);
                *reinterpret_cast<__half2*>(Cl + i1) = __halves2half2(l2, l3);
            }
        }
    }
}

// ---------------------------------------------------------------------------
__global__ void cvt_kernel(const float* __restrict__ in, __half* __restrict__ oh,
                           __half* __restrict__ ol, long long n)
{
    long long i = (long long)blockIdx.x * blockDim.x + threadIdx.x;
    if (i < n) {
        __half h, l;
        fsplit(in[i], h, l);
        oh[i] = h; ol[i] = l;
    }
}

// ---------------------------------------------------------------------------
__global__ void transpose_cvt_kernel(const float* __restrict__ in,
                                     __half* __restrict__ oh, __half* __restrict__ ol,
                                     int R, int Cc)
{
    __shared__ float tsm[32][33];
    const int z = blockIdx.z;
    const int r0 = blockIdx.y * 32, c0 = blockIdx.x * 32;
    const float* I = in + (long long)z * R * Cc;
    const long long obase = (long long)z * R * Cc;
    const int tx = threadIdx.x, ty = threadIdx.y;
#pragma unroll
    for (int i = 0; i < 32; i += 8)
        tsm[ty + i][tx] = I[(long long)(r0 + ty + i) * Cc + c0 + tx];
    __syncthreads();
#pragma unroll
    for (int i = 0; i < 32; i += 8) {
        __half h, l;
        fsplit(tsm[tx][ty + i], h, l);
        long long o = obase + (long long)(c0 + ty + i) * R + r0 + tx;
        oh[o] = h; ol[o] = l;
    }
}

// ---------------------------------------------------------------------------
// Causal row softmax, SINGLE exp per element:
// pass 1: e = exp(s - mx) stored back into the fp32 scores row + sum
// pass 2: read e, scale, split to hi/lo halves; zero-fill to 128 boundary.
// ---------------------------------------------------------------------------
__global__ void softmax_kernel(float* __restrict__ scores,
                               __half* __restrict__ ph, __half* __restrict__ pl)
{
    const int warp = threadIdx.x >> 5;
    const int lane = threadIdx.x & 31;
    const long long r = (long long)blockIdx.x * (blockDim.x >> 5) + warp;
    const int s = (int)(r & (SEQL - 1));
    const int len = s + 1;
    float* row = scores + r * SEQL;
    __half* rh = ph + r * SEQL;
    __half* rl = pl + r * SEQL;

    float mx = -INFINITY;
    for (int j = lane; j < len; j += 32) mx = fmaxf(mx, row[j]);
#pragma unroll
    for (int o = 16; o > 0; o >>= 1) mx = fmaxf(mx, __shfl_xor_sync(0xffffffffu, mx, o));

    float sum = 0.f;
    for (int j = lane; j < len; j += 32) {
        float e = __expf(row[j] - mx);
        row[j] = e;
        sum += e;
    }
#pragma unroll
    for (int o = 16; o > 0; o >>= 1) sum += __shfl_xor_sync(0xffffffffu, sum, o);

    const float inv = 1.0f / sum;
    for (int j = lane; j < len; j += 32) {
        float p = row[j] * inv;
        __half h, l;
        fsplit(p, h, l);
        rh[j] = h; rl[j] = l;
    }
    const int zend = ((s >> 7) + 1) << 7;
    for (int j = len + lane; j < zend; j += 32) {
        rh[j] = __float2half_rn(0.f); rl[j] = __float2half_rn(0.f);
    }
}

// ---------------------------------------------------------------------------
extern "C" void kernel_launch(void* const* d_in, const int* in_sizes, int n_in,
                              void* d_out, int out_size)
{
    const float* x   = (const float*)d_in[0];
    const float* Wd  = (const float*)d_in[1];
    const float* Wuk = (const float*)d_in[2];
    const float* Wuv = (const float*)d_in[3];
    const float* Wq  = (const float*)d_in[4];
    const float* Wo  = (const float*)d_in[5];
    float* out = (float*)d_out;

#define SYM(p, s) cudaGetSymbolAddress((void**)&p, s)
    __half *xh, *xl, *wdh, *wdl, *wqh, *wql, *wuvh, *wuvl, *woh, *wol, *wukTh, *wukTl;
    __half *lath, *latl, *latTh, *latTl, *qh, *ql, *qlath, *qlatl;
    __half *attnh, *attnl, *ctxh, *ctxl, *vh, *vl;
    float *lat, *sc;
    SYM(xh, g_xh); SYM(xl, g_xl); SYM(wdh, g_wdh); SYM(wdl, g_wdl);
    SYM(wqh, g_wqh); SYM(wql, g_wql); SYM(wuvh, g_wuvh); SYM(wuvl, g_wuvl);
    SYM(woh, g_woh); SYM(wol, g_wol); SYM(wukTh, g_wukTh); SYM(wukTl, g_wukTl);
    SYM(lat, g_lat); SYM(lath, g_lath); SYM(latl, g_latl);
    SYM(latTh, g_latTh); SYM(latTl, g_latTl);
    SYM(qh, g_qh); SYM(ql, g_ql); SYM(qlath, g_qlath); SYM(qlatl, g_qlatl);
    SYM(sc, g_scores); SYM(attnh, g_attnh); SYM(attnl, g_attnl);
    SYM(ctxh, g_ctxh); SYM(ctxl, g_ctxl); SYM(vh, g_vh); SYM(vl, g_vl);
#undef SYM

    static int attr_done = 0;
    if (!attr_done) {
        cudaFuncSetAttribute(mma_gemm<0, 0>, cudaFuncAttributeMaxDynamicSharedMemorySize, SMEM_BYTES);
        cudaFuncSetAttribute(mma_gemm<0, 1>, cudaFuncAttributeMaxDynamicSharedMemorySize, SMEM_BYTES);
        cudaFuncSetAttribute(mma_gemm<0, 2>, cudaFuncAttributeMaxDynamicSharedMemorySize, SMEM_BYTES);
        cudaFuncSetAttribute(mma_gemm<1, 1>, cudaFuncAttributeMaxDynamicSharedMemorySize, SMEM_BYTES);
        cudaFuncSetAttribute(mma_gemm<2, 0>, cudaFuncAttributeMaxDynamicSharedMemorySize, SMEM_BYTES);
        cudaFuncSetAttribute(mma_gemm<3, 1>, cudaFuncAttributeMaxDynamicSharedMemorySize, SMEM_BYTES);
        cudaFuncSetAttribute(mma_gemm<4, 1>, cudaFuncAttributeMaxDynamicSharedMemorySize, SMEM_BYTES);
        attr_done = 1;
    }

    const int MROWS = SB * SEQL;  // 4096
    const dim3 blk(256);
    const float inv_sqrt_dh = 0.08838834764831845f;

    // C0: split inputs/weights
    {
        long long n;
        n = (long long)SB * SEQL * DMODEL;
        cvt_kernel<<<(unsigned)((n + 255) / 256), 256>>>(x, xh, xl, n);
        n = (long long)CLAT * DMODEL;
        cvt_kernel<<<(unsigned)((n + 255) / 256), 256>>>(Wd, wdh, wdl, n);
        n = (long long)HDTOT * DMODEL;
        cvt_kernel<<<(unsigned)((n + 255) / 256), 256>>>(Wq, wqh, wql, n);
        n = (long long)HDTOT * CLAT;
        cvt_kernel<<<(unsigned)((n + 255) / 256), 256>>>(Wuv, wuvh, wuvl, n);
        n = (long long)DMODEL * HDTOT;
        cvt_kernel<<<(unsigned)((n + 255) / 256), 256>>>(Wo, woh, wol, n);
    }
    // T2: wukT halves
    transpose_cvt_kernel<<<dim3(CLAT / 32, DHD / 32, NH), dim3(32, 8)>>>(
        Wuk, wukTh, wukTl, DHD, CLAT);

    // G1: latents = x @ Wd^T   (fp32 + halves)
    mma_gemm<0, 2><<<dim3(CLAT / BN, MROWS / BM, 1), blk, SMEM_BYTES>>>(
        xh, xl, wdh, wdl, lat, lath, latl, DMODEL, DMODEL, DMODEL, CLAT, 1.f);

    // T1: latT halves
    transpose_cvt_kernel<<<dim3(CLAT / 32, SEQL / 32, SB), dim3(32, 8)>>>(
        lat, latTh, latTl, SEQL, CLAT);

    // G2: q = x @ Wq^T  (halves out)
    mma_gemm<0, 1><<<dim3(HDTOT / BN, MROWS / BM, 1), blk, SMEM_BYTES>>>(
        xh, xl, wqh, wql, nullptr, qh, ql, DMODEL, DMODEL, DMODEL, HDTOT, 1.f);

    // G3: q_lat[z] = q_h @ wukT[h]^T   (K=128, halves out)
    mma_gemm<1, 1><<<dim3(CLAT / BN, SEQL / BM, SB * NH), blk, SMEM_BYTES>>>(
        qh, ql, wukTh, wukTl, nullptr, qlath, qlatl, DHD, HDTOT, DHD, CLAT, 1.f);

    // G4: scores = q_lat @ latents^T / sqrt(dh)  (causal, fp32 out)
    mma_gemm<2, 0><<<dim3(SEQL / BN, SEQL / BM, SB * NH), blk, SMEM_BYTES>>>(
        qlath, qlatl, lath, latl, sc, nullptr, nullptr, CLAT, CLAT, CLAT, SEQL, inv_sqrt_dh);

    // G5: softmax -> attn halves (single exp)
    softmax_kernel<<<(unsigned)((long long)SB * NH * SEQL / 8), 256>>>(sc, attnh, attnl);

    // G6: ctx = attn @ latT^T  (K_eff per row tile, halves out)
    mma_gemm<3, 1><<<dim3(CLAT / BN, SEQL / BM, SB * NH), blk, SMEM_BYTES>>>(
        attnh, attnl, latTh, latTl, nullptr, ctxh, ctxl, SEQL, SEQL, SEQL, CLAT, 1.f);

    // G7: v_h = ctx @ Wuv_h^T  (halves out)
    mma_gemm<4, 1><<<dim3(DHD / BN, SEQL / BM, SB * NH), blk, SMEM_BYTES>>>(
        ctxh, ctxl, wuvh, wuvl, nullptr, vh, vl, CLAT, CLAT, CLAT, HDTOT, 1.f);

    // G8: out = v @ Wo^T  (fp32 out)
    mma_gemm<0, 0><<<dim3(DMODEL / BN, MROWS / BM, 1), blk, SMEM_BYTES>>>(
        vh, vl, woh, wol, out, nullptr, nullptr, HDTOT, HDTOT, HDTOT, DMODEL, 1.f);
}